// round 3
// baseline (speedup 1.0000x reference)
#include <cuda_runtime.h>
#include <cuda_bf16.h>
#include <math.h>

// Problem constants
#define ES    8
#define DS    1024
#define HS    2048
#define DOUTS 1024
#define TS    8192
#define CAP   8192   // worst-case tokens per expert (duplicates merge)

// ---------------- scratch (device globals; allocations are banned) ----------
__device__ int   g_cnt[ES];
__device__ int   g_tok[ES * CAP];
__device__ float g_wt [ES * CAP];
__device__ int   g_slot0[TS];
__device__ int   g_slot1[TS];
__device__ float g_Hb[(size_t)ES * CAP * HS];    // h = silu(g)*u*w  (512 MB)
__device__ float g_O[(size_t)ES * CAP * DOUTS];  // down proj output (256 MB)

// ---------------- routing ----------------------------------------------------
__global__ void zero_cnt_kernel() {
    if (threadIdx.x < ES) g_cnt[threadIdx.x] = 0;
}

// NOTE: top_k_indices is int32 (JAX default int width), NOT int64.
__global__ void build_kernel(const int* __restrict__ idx,
                             const float* __restrict__ w) {
    int t = blockIdx.x * blockDim.x + threadIdx.x;
    if (t >= TS) return;
    int e0 = idx[2 * t];
    int e1 = idx[2 * t + 1];
    float w0 = w[2 * t];
    float w1 = w[2 * t + 1];
    // range guard (defensive; avoids wild atomics if dtype assumption shifts)
    if ((unsigned)e0 >= ES) e0 = 0;
    if ((unsigned)e1 >= ES) e1 = 0;
    if (e0 == e1) {
        int s = atomicAdd(&g_cnt[e0], 1);
        g_tok[e0 * CAP + s] = t;
        g_wt [e0 * CAP + s] = w0 + w1;
        g_slot0[t] = e0 * CAP + s;
        g_slot1[t] = -1;
    } else {
        int s0 = atomicAdd(&g_cnt[e0], 1);
        g_tok[e0 * CAP + s0] = t;
        g_wt [e0 * CAP + s0] = w0;
        int s1 = atomicAdd(&g_cnt[e1], 1);
        g_tok[e1 * CAP + s1] = t;
        g_wt [e1 * CAP + s1] = w1;
        g_slot0[t] = e0 * CAP + s0;
        g_slot1[t] = e1 * CAP + s1;
    }
}

// ---------------- fused gate+up GEMM -----------------------------------------
// For expert e, token tile of 128 gathered rows, N-tile of 64 H-columns:
//   g = X_tile @ Wg_e[n0:n0+64,:]^T ; u = X_tile @ Wu_e[...]^T
//   h = silu(g) * u * combine_weight  -> g_Hb
__global__ __launch_bounds__(256, 1)
void gateup_kernel(const float* __restrict__ X,
                   const float* __restrict__ Wg,
                   const float* __restrict__ Wu) {
    int e = blockIdx.z;
    int cnt = g_cnt[e];
    int m0 = blockIdx.x * 128;
    if (m0 >= cnt) return;
    int n0 = blockIdx.y * 64;

    __shared__ float As[8][128];
    __shared__ float Bg[8][64];
    __shared__ float Bu[8][64];

    int tid = threadIdx.x;

    // A loader: 128 rows x 8 k, one float4 per thread
    int rowA  = tid >> 1;
    int ksegA = (tid & 1) * 4;
    int slotA = m0 + rowA;
    int token = (slotA < cnt) ? g_tok[e * CAP + slotA] : 0;
    const float* Arow = X + (size_t)token * DS;

    // B loaders: threads 0..127 -> Wg panel, 128..255 -> Wu panel
    int rowB  = (tid & 127) >> 1;    // 0..63
    int ksegB = (tid & 1) * 4;
    bool doU = (tid >= 128);
    const float* Brow = (doU ? Wu : Wg) + ((size_t)e * HS + n0 + rowB) * DS;

    int tx = tid & 15;   // n micro (4 cols)
    int ty = tid >> 4;   // m micro (8 rows)

    float accG[8][4], accU[8][4];
#pragma unroll
    for (int i = 0; i < 8; i++)
#pragma unroll
        for (int j = 0; j < 4; j++) { accG[i][j] = 0.f; accU[i][j] = 0.f; }

    for (int k0 = 0; k0 < DS; k0 += 8) {
        float4 av = *(const float4*)(Arow + k0 + ksegA);
        float4 bv = *(const float4*)(Brow + k0 + ksegB);
        As[ksegA + 0][rowA] = av.x;
        As[ksegA + 1][rowA] = av.y;
        As[ksegA + 2][rowA] = av.z;
        As[ksegA + 3][rowA] = av.w;
        float (*Bsp)[64] = doU ? Bu : Bg;
        Bsp[ksegB + 0][rowB] = bv.x;
        Bsp[ksegB + 1][rowB] = bv.y;
        Bsp[ksegB + 2][rowB] = bv.z;
        Bsp[ksegB + 3][rowB] = bv.w;
        __syncthreads();
#pragma unroll
        for (int kk = 0; kk < 8; kk++) {
            float4 a0 = *(const float4*)&As[kk][ty * 8];
            float4 a1 = *(const float4*)&As[kk][ty * 8 + 4];
            float4 bg = *(const float4*)&Bg[kk][tx * 4];
            float4 bu = *(const float4*)&Bu[kk][tx * 4];
            float am[8] = {a0.x, a0.y, a0.z, a0.w, a1.x, a1.y, a1.z, a1.w};
            float bgn[4] = {bg.x, bg.y, bg.z, bg.w};
            float bun[4] = {bu.x, bu.y, bu.z, bu.w};
#pragma unroll
            for (int i = 0; i < 8; i++)
#pragma unroll
                for (int j = 0; j < 4; j++) {
                    accG[i][j] = fmaf(am[i], bgn[j], accG[i][j]);
                    accU[i][j] = fmaf(am[i], bun[j], accU[i][j]);
                }
        }
        __syncthreads();
    }

    int ecap = e * CAP;
#pragma unroll
    for (int mi = 0; mi < 8; mi++) {
        int slot = m0 + ty * 8 + mi;
        if (slot >= cnt) continue;
        float wv = g_wt[ecap + slot];
        float* hr = g_Hb + (size_t)(ecap + slot) * HS + n0 + tx * 4;
        float4 hv;
        float g0 = accG[mi][0], g1 = accG[mi][1], g2 = accG[mi][2], g3 = accG[mi][3];
        hv.x = (g0 / (1.0f + __expf(-g0))) * accU[mi][0] * wv;
        hv.y = (g1 / (1.0f + __expf(-g1))) * accU[mi][1] * wv;
        hv.z = (g2 / (1.0f + __expf(-g2))) * accU[mi][2] * wv;
        hv.w = (g3 / (1.0f + __expf(-g3))) * accU[mi][3] * wv;
        *(float4*)hr = hv;
    }
}

// ---------------- down GEMM: O = H @ Wd^T ------------------------------------
__global__ __launch_bounds__(256, 1)
void down_kernel(const float* __restrict__ Wd) {
    int e = blockIdx.z;
    int cnt = g_cnt[e];
    int m0 = blockIdx.x * 128;
    if (m0 >= cnt) return;
    int n0 = blockIdx.y * 128;

    const float* W = Wd + (size_t)e * DOUTS * HS;

    __shared__ float As[8][128];
    __shared__ float Bs[8][128];

    int tid  = threadIdx.x;
    int rowA = tid >> 1;
    int kseg = (tid & 1) * 4;

    const float* Arow = g_Hb + (size_t)(e * CAP + m0 + rowA) * HS;
    const float* Brow = W + (size_t)(n0 + rowA) * HS;

    int tx = tid & 15;
    int ty = tid >> 4;

    float acc[8][8];
#pragma unroll
    for (int i = 0; i < 8; i++)
#pragma unroll
        for (int j = 0; j < 8; j++) acc[i][j] = 0.f;

    for (int k0 = 0; k0 < HS; k0 += 8) {
        float4 av = *(const float4*)(Arow + k0 + kseg);
        float4 bv = *(const float4*)(Brow + k0 + kseg);
        As[kseg + 0][rowA] = av.x;
        As[kseg + 1][rowA] = av.y;
        As[kseg + 2][rowA] = av.z;
        As[kseg + 3][rowA] = av.w;
        Bs[kseg + 0][rowA] = bv.x;
        Bs[kseg + 1][rowA] = bv.y;
        Bs[kseg + 2][rowA] = bv.z;
        Bs[kseg + 3][rowA] = bv.w;
        __syncthreads();
#pragma unroll
        for (int kk = 0; kk < 8; kk++) {
            float4 a0 = *(const float4*)&As[kk][ty * 8];
            float4 a1 = *(const float4*)&As[kk][ty * 8 + 4];
            float4 b0 = *(const float4*)&Bs[kk][tx * 8];
            float4 b1 = *(const float4*)&Bs[kk][tx * 8 + 4];
            float am[8] = {a0.x, a0.y, a0.z, a0.w, a1.x, a1.y, a1.z, a1.w};
            float bn[8] = {b0.x, b0.y, b0.z, b0.w, b1.x, b1.y, b1.z, b1.w};
#pragma unroll
            for (int i = 0; i < 8; i++)
#pragma unroll
                for (int j = 0; j < 8; j++)
                    acc[i][j] = fmaf(am[i], bn[j], acc[i][j]);
        }
        __syncthreads();
    }

    int ecap = e * CAP;
#pragma unroll
    for (int mi = 0; mi < 8; mi++) {
        int slot = m0 + ty * 8 + mi;
        if (slot >= cnt) continue;
        float* orow = g_O + (size_t)(ecap + slot) * DOUTS + n0 + tx * 8;
        float4 v0 = {acc[mi][0], acc[mi][1], acc[mi][2], acc[mi][3]};
        float4 v1 = {acc[mi][4], acc[mi][5], acc[mi][6], acc[mi][7]};
        *(float4*)orow       = v0;
        *(float4*)(orow + 4) = v1;
    }
}

// ---------------- final combine ---------------------------------------------
__global__ void combine_kernel(float* __restrict__ out) {
    int i = blockIdx.x * blockDim.x + threadIdx.x;  // over TS*DOUTS/4
    if (i >= TS * (DOUTS / 4)) return;
    int t  = i / (DOUTS / 4);
    int d4 = i % (DOUTS / 4);
    const float4* O4 = (const float4*)g_O;
    float4 a = O4[(size_t)g_slot0[t] * (DOUTS / 4) + d4];
    int s1 = g_slot1[t];
    if (s1 >= 0) {
        float4 b = O4[(size_t)s1 * (DOUTS / 4) + d4];
        a.x += b.x; a.y += b.y; a.z += b.z; a.w += b.w;
    }
    ((float4*)out)[i] = a;
}

// ---------------- launch -----------------------------------------------------
extern "C" void kernel_launch(void* const* d_in, const int* in_sizes, int n_in,
                              void* d_out, int out_size) {
    const float* X   = (const float*)d_in[0];   // [T, D]
    const int*   idx = (const int*)d_in[1];     // [T, K] int32 (JAX default)
    const float* wts = (const float*)d_in[2];   // [T, K]
    const float* Wg  = (const float*)d_in[3];   // [E, H, D]
    const float* Wu  = (const float*)d_in[4];   // [E, H, D]
    const float* Wd  = (const float*)d_in[5];   // [E, DOUT, H]
    float* out = (float*)d_out;                 // [T, DOUT]

    zero_cnt_kernel<<<1, 32>>>();
    build_kernel<<<(TS + 255) / 256, 256>>>(idx, wts);

    dim3 gUp(CAP / 128, HS / 64, ES);           // 64 x 32 x 8 (early-exit on count)
    gateup_kernel<<<gUp, 256>>>(X, Wg, Wu);

    dim3 gDn(CAP / 128, DOUTS / 128, ES);       // 64 x 8 x 8
    down_kernel<<<gDn, 256>>>(Wd);

    combine_kernel<<<(TS * (DOUTS / 4) + 255) / 256, 256>>>(out);
}

// round 10
// speedup vs baseline: 1.1819x; 1.1819x over previous
#include <cuda_runtime.h>
#include <math.h>

// Problem constants
#define ES    8
#define DS    1024
#define HS    2048
#define DOUTS 1024
#define TS    8192
#define CAP   8192

// ---------------- scratch (device globals; allocations banned) ----------
__device__ int   g_cnt[ES];
__device__ int   g_tok[ES * CAP];
__device__ float g_wt [ES * CAP];
__device__ int   g_slot0[TS];
__device__ int   g_slot1[TS];
__device__ float g_Hb[(size_t)ES * CAP * HS];    // h = silu(g)*u*w  (512 MB)
__device__ float g_O[(size_t)ES * CAP * DOUTS];  // down proj output (256 MB)

// ---------------- routing ----------------------------------------------------
__global__ void zero_cnt_kernel() {
    if (threadIdx.x < ES) g_cnt[threadIdx.x] = 0;
}

__global__ void build_kernel(const int* __restrict__ idx,
                             const float* __restrict__ w) {
    int t = blockIdx.x * blockDim.x + threadIdx.x;
    if (t >= TS) return;
    int e0 = idx[2 * t];
    int e1 = idx[2 * t + 1];
    float w0 = w[2 * t];
    float w1 = w[2 * t + 1];
    if ((unsigned)e0 >= ES) e0 = 0;
    if ((unsigned)e1 >= ES) e1 = 0;
    if (e0 == e1) {
        int s = atomicAdd(&g_cnt[e0], 1);
        g_tok[e0 * CAP + s] = t;
        g_wt [e0 * CAP + s] = w0 + w1;
        g_slot0[t] = e0 * CAP + s;
        g_slot1[t] = -1;
    } else {
        int s0 = atomicAdd(&g_cnt[e0], 1);
        g_tok[e0 * CAP + s0] = t;
        g_wt [e0 * CAP + s0] = w0;
        int s1 = atomicAdd(&g_cnt[e1], 1);
        g_tok[e1 * CAP + s1] = t;
        g_wt [e1 * CAP + s1] = w1;
        g_slot0[t] = e0 * CAP + s0;
        g_slot1[t] = e1 * CAP + s1;
    }
}

// ---------------- fused gate+up GEMM (double-buffered, prefetch) -------------
// Tile: 128 gathered rows x 64 H-cols; dual accumulators (gate & up).
__global__ __launch_bounds__(256, 2)
void gateup_kernel(const float* __restrict__ X,
                   const float* __restrict__ Wg,
                   const float* __restrict__ Wu) {
    int e = blockIdx.z;
    int cnt = g_cnt[e];
    int m0 = blockIdx.x * 128;
    if (m0 >= cnt) return;
    int n0 = blockIdx.y * 64;

    __shared__ float As[2][8][128];
    __shared__ float Bg[2][8][64];
    __shared__ float Bu[2][8][64];

    int tid = threadIdx.x;

    // A loader: 128 rows x 8 k, one float4 per thread
    int rowA  = tid >> 1;
    int ksegA = (tid & 1) * 4;
    int slotA = m0 + rowA;
    int token = (slotA < cnt) ? g_tok[e * CAP + slotA] : 0;
    const float* Arow = X + (size_t)token * DS;

    // B loaders: threads 0..127 -> Wg panel, 128..255 -> Wu panel
    int rowB  = (tid & 127) >> 1;    // 0..63
    int ksegB = (tid & 1) * 4;
    bool doU = (tid >= 128);
    const float* Brow = (doU ? Wu : Wg) + ((size_t)e * HS + n0 + rowB) * DS;

    int tx = tid & 15;   // n micro (4 cols)
    int ty = tid >> 4;   // m micro (8 rows)

    float accG[8][4], accU[8][4];
#pragma unroll
    for (int i = 0; i < 8; i++)
#pragma unroll
        for (int j = 0; j < 4; j++) { accG[i][j] = 0.f; accU[i][j] = 0.f; }

    // prime: prefetch tile 0, store to buf 0
    float4 av = *(const float4*)(Arow + ksegA);
    float4 bv = *(const float4*)(Brow + ksegB);
    As[0][ksegA + 0][rowA] = av.x;
    As[0][ksegA + 1][rowA] = av.y;
    As[0][ksegA + 2][rowA] = av.z;
    As[0][ksegA + 3][rowA] = av.w;
    if (doU) {
        Bu[0][ksegB + 0][rowB] = bv.x;
        Bu[0][ksegB + 1][rowB] = bv.y;
        Bu[0][ksegB + 2][rowB] = bv.z;
        Bu[0][ksegB + 3][rowB] = bv.w;
    } else {
        Bg[0][ksegB + 0][rowB] = bv.x;
        Bg[0][ksegB + 1][rowB] = bv.y;
        Bg[0][ksegB + 2][rowB] = bv.z;
        Bg[0][ksegB + 3][rowB] = bv.w;
    }
    __syncthreads();

    for (int k0 = 0; k0 < DS; k0 += 8) {
        int buf = (k0 >> 3) & 1;
        // prefetch next tile into registers (overlaps with compute)
        if (k0 + 8 < DS) {
            av = *(const float4*)(Arow + k0 + 8 + ksegA);
            bv = *(const float4*)(Brow + k0 + 8 + ksegB);
        }
#pragma unroll
        for (int kk = 0; kk < 8; kk++) {
            float4 a0 = *(const float4*)&As[buf][kk][ty * 8];
            float4 a1 = *(const float4*)&As[buf][kk][ty * 8 + 4];
            float4 bgv = *(const float4*)&Bg[buf][kk][tx * 4];
            float4 buv = *(const float4*)&Bu[buf][kk][tx * 4];
            float am0 = a0.x, am1 = a0.y, am2 = a0.z, am3 = a0.w;
            float am4 = a1.x, am5 = a1.y, am6 = a1.z, am7 = a1.w;
#pragma unroll
            for (int j = 0; j < 4; j++) {
                float bgn = (j == 0) ? bgv.x : (j == 1) ? bgv.y : (j == 2) ? bgv.z : bgv.w;
                float bun = (j == 0) ? buv.x : (j == 1) ? buv.y : (j == 2) ? buv.z : buv.w;
                accG[0][j] = fmaf(am0, bgn, accG[0][j]);
                accG[1][j] = fmaf(am1, bgn, accG[1][j]);
                accG[2][j] = fmaf(am2, bgn, accG[2][j]);
                accG[3][j] = fmaf(am3, bgn, accG[3][j]);
                accG[4][j] = fmaf(am4, bgn, accG[4][j]);
                accG[5][j] = fmaf(am5, bgn, accG[5][j]);
                accG[6][j] = fmaf(am6, bgn, accG[6][j]);
                accG[7][j] = fmaf(am7, bgn, accG[7][j]);
                accU[0][j] = fmaf(am0, bun, accU[0][j]);
                accU[1][j] = fmaf(am1, bun, accU[1][j]);
                accU[2][j] = fmaf(am2, bun, accU[2][j]);
                accU[3][j] = fmaf(am3, bun, accU[3][j]);
                accU[4][j] = fmaf(am4, bun, accU[4][j]);
                accU[5][j] = fmaf(am5, bun, accU[5][j]);
                accU[6][j] = fmaf(am6, bun, accU[6][j]);
                accU[7][j] = fmaf(am7, bun, accU[7][j]);
            }
        }
        // store prefetched tile into the other buffer, then one sync
        if (k0 + 8 < DS) {
            int nb = buf ^ 1;
            As[nb][ksegA + 0][rowA] = av.x;
            As[nb][ksegA + 1][rowA] = av.y;
            As[nb][ksegA + 2][rowA] = av.z;
            As[nb][ksegA + 3][rowA] = av.w;
            if (doU) {
                Bu[nb][ksegB + 0][rowB] = bv.x;
                Bu[nb][ksegB + 1][rowB] = bv.y;
                Bu[nb][ksegB + 2][rowB] = bv.z;
                Bu[nb][ksegB + 3][rowB] = bv.w;
            } else {
                Bg[nb][ksegB + 0][rowB] = bv.x;
                Bg[nb][ksegB + 1][rowB] = bv.y;
                Bg[nb][ksegB + 2][rowB] = bv.z;
                Bg[nb][ksegB + 3][rowB] = bv.w;
            }
            __syncthreads();
        }
    }

    int ecap = e * CAP;
#pragma unroll
    for (int mi = 0; mi < 8; mi++) {
        int slot = m0 + ty * 8 + mi;
        if (slot >= cnt) continue;
        float wv = g_wt[ecap + slot];
        float* hr = g_Hb + (size_t)(ecap + slot) * HS + n0 + tx * 4;
        float g0 = accG[mi][0], g1 = accG[mi][1], g2 = accG[mi][2], g3 = accG[mi][3];
        float4 hv;
        hv.x = (g0 / (1.0f + __expf(-g0))) * accU[mi][0] * wv;
        hv.y = (g1 / (1.0f + __expf(-g1))) * accU[mi][1] * wv;
        hv.z = (g2 / (1.0f + __expf(-g2))) * accU[mi][2] * wv;
        hv.w = (g3 / (1.0f + __expf(-g3))) * accU[mi][3] * wv;
        *(float4*)hr = hv;
    }
}

// ---------------- down GEMM: O = H @ Wd^T (double-buffered, prefetch) --------
__global__ __launch_bounds__(256, 2)
void down_kernel(const float* __restrict__ Wd) {
    int e = blockIdx.z;
    int cnt = g_cnt[e];
    int m0 = blockIdx.x * 128;
    if (m0 >= cnt) return;
    int n0 = blockIdx.y * 128;

    const float* W = Wd + (size_t)e * DOUTS * HS;

    __shared__ float As[2][8][128];
    __shared__ float Bs[2][8][128];

    int tid  = threadIdx.x;
    int rowA = tid >> 1;
    int kseg = (tid & 1) * 4;

    const float* Arow = g_Hb + (size_t)(e * CAP + m0 + rowA) * HS;
    const float* Brow = W + (size_t)(n0 + rowA) * HS;

    int tx = tid & 15;
    int ty = tid >> 4;

    float acc[8][8];
#pragma unroll
    for (int i = 0; i < 8; i++)
#pragma unroll
        for (int j = 0; j < 8; j++) acc[i][j] = 0.f;

    float4 av = *(const float4*)(Arow + kseg);
    float4 bv = *(const float4*)(Brow + kseg);
    As[0][kseg + 0][rowA] = av.x;
    As[0][kseg + 1][rowA] = av.y;
    As[0][kseg + 2][rowA] = av.z;
    As[0][kseg + 3][rowA] = av.w;
    Bs[0][kseg + 0][rowA] = bv.x;
    Bs[0][kseg + 1][rowA] = bv.y;
    Bs[0][kseg + 2][rowA] = bv.z;
    Bs[0][kseg + 3][rowA] = bv.w;
    __syncthreads();

    for (int k0 = 0; k0 < HS; k0 += 8) {
        int buf = (k0 >> 3) & 1;
        if (k0 + 8 < HS) {
            av = *(const float4*)(Arow + k0 + 8 + kseg);
            bv = *(const float4*)(Brow + k0 + 8 + kseg);
        }
#pragma unroll
        for (int kk = 0; kk < 8; kk++) {
            float4 a0 = *(const float4*)&As[buf][kk][ty * 8];
            float4 a1 = *(const float4*)&As[buf][kk][ty * 8 + 4];
            float4 b0 = *(const float4*)&Bs[buf][kk][tx * 8];
            float4 b1 = *(const float4*)&Bs[buf][kk][tx * 8 + 4];
            float am0 = a0.x, am1 = a0.y, am2 = a0.z, am3 = a0.w;
            float am4 = a1.x, am5 = a1.y, am6 = a1.z, am7 = a1.w;
#pragma unroll
            for (int j = 0; j < 8; j++) {
                float bn = (j == 0) ? b0.x : (j == 1) ? b0.y : (j == 2) ? b0.z : (j == 3) ? b0.w
                          : (j == 4) ? b1.x : (j == 5) ? b1.y : (j == 6) ? b1.z : b1.w;
                acc[0][j] = fmaf(am0, bn, acc[0][j]);
                acc[1][j] = fmaf(am1, bn, acc[1][j]);
                acc[2][j] = fmaf(am2, bn, acc[2][j]);
                acc[3][j] = fmaf(am3, bn, acc[3][j]);
                acc[4][j] = fmaf(am4, bn, acc[4][j]);
                acc[5][j] = fmaf(am5, bn, acc[5][j]);
                acc[6][j] = fmaf(am6, bn, acc[6][j]);
                acc[7][j] = fmaf(am7, bn, acc[7][j]);
            }
        }
        if (k0 + 8 < HS) {
            int nb = buf ^ 1;
            As[nb][kseg + 0][rowA] = av.x;
            As[nb][kseg + 1][rowA] = av.y;
            As[nb][kseg + 2][rowA] = av.z;
            As[nb][kseg + 3][rowA] = av.w;
            Bs[nb][kseg + 0][rowA] = bv.x;
            Bs[nb][kseg + 1][rowA] = bv.y;
            Bs[nb][kseg + 2][rowA] = bv.z;
            Bs[nb][kseg + 3][rowA] = bv.w;
            __syncthreads();
        }
    }

    int ecap = e * CAP;
#pragma unroll
    for (int mi = 0; mi < 8; mi++) {
        int slot = m0 + ty * 8 + mi;
        if (slot >= cnt) continue;
        float* orow = g_O + (size_t)(ecap + slot) * DOUTS + n0 + tx * 8;
        float4 v0, v1;
        v0.x = acc[mi][0]; v0.y = acc[mi][1]; v0.z = acc[mi][2]; v0.w = acc[mi][3];
        v1.x = acc[mi][4]; v1.y = acc[mi][5]; v1.z = acc[mi][6]; v1.w = acc[mi][7];
        *(float4*)orow       = v0;
        *(float4*)(orow + 4) = v1;
    }
}

// ---------------- final combine ---------------------------------------------
__global__ void combine_kernel(float* __restrict__ out) {
    int i = blockIdx.x * blockDim.x + threadIdx.x;  // over TS*DOUTS/4
    if (i >= TS * (DOUTS / 4)) return;
    int t  = i / (DOUTS / 4);
    int d4 = i % (DOUTS / 4);
    const float4* O4 = (const float4*)g_O;
    float4 a = O4[(size_t)g_slot0[t] * (DOUTS / 4) + d4];
    int s1 = g_slot1[t];
    if (s1 >= 0) {
        float4 b = O4[(size_t)s1 * (DOUTS / 4) + d4];
        a.x += b.x; a.y += b.y; a.z += b.z; a.w += b.w;
    }
    ((float4*)out)[i] = a;
}

// ---------------- launch -----------------------------------------------------
extern "C" void kernel_launch(void* const* d_in, const int* in_sizes, int n_in,
                              void* d_out, int out_size) {
    const float* X   = (const float*)d_in[0];   // [T, D]
    const int*   idx = (const int*)d_in[1];     // [T, K] int32 (JAX default)
    const float* wts = (const float*)d_in[2];   // [T, K]
    const float* Wg  = (const float*)d_in[3];   // [E, H, D]
    const float* Wu  = (const float*)d_in[4];   // [E, H, D]
    const float* Wd  = (const float*)d_in[5];   // [E, DOUT, H]
    float* out = (float*)d_out;                 // [T, DOUT]

    zero_cnt_kernel<<<1, 32>>>();
    build_kernel<<<(TS + 255) / 256, 256>>>(idx, wts);

    dim3 gUp(CAP / 128, HS / 64, ES);           // 64 x 32 x 8 (early-exit on count)
    gateup_kernel<<<gUp, 256>>>(X, Wg, Wu);

    dim3 gDn(CAP / 128, DOUTS / 128, ES);       // 64 x 8 x 8
    down_kernel<<<gDn, 256>>>(Wd);

    combine_kernel<<<(TS * (DOUTS / 4) + 255) / 256, 256>>>(out);
}